// round 1
// baseline (speedup 1.0000x reference)
#include <cuda_runtime.h>
#include <math.h>

#define BB 2
#define SS 2048
#define DIM 1536
#define NH 12
#define HD 128
#define SIGMA 12
#define M_TOT (BB * SS)      // 4096
#define N_QKV (3 * DIM)      // 4608

// Scratch (allocation-free rule: __device__ globals)
__device__ float g_qkv[(size_t)M_TOT * N_QKV];   // (b*s, [q|k|v] x H x HD)
__device__ float g_att[(size_t)M_TOT * DIM];     // (b*s, h*hd)

// ---------------------------------------------------------------------------
// Tiled fp32 GEMM with bias: C[M,N] = A[M,K] @ W[K,N] + bias[N]
// BM=BN=128, BK=8, TM=TN=8, 256 threads. Requires M%128==0, N%128==0, K%8==0.
// ---------------------------------------------------------------------------
template <int BM, int BN, int BK, int TM, int TN>
__global__ __launch_bounds__((BM / TM) * (BN / TN))
void sgemm_bias(int M, int N, int K,
                const float* __restrict__ A,
                const float* __restrict__ W,
                const float* __restrict__ bias,
                float* __restrict__ C) {
    __shared__ float As[BK * BM];   // transposed: [k][m]
    __shared__ float Bs[BK * BN];   // [k][n]

    const int cRow = blockIdx.y;
    const int cCol = blockIdx.x;
    const int tid = threadIdx.x;

    const int threadCol = tid % (BN / TN);   // 0..15
    const int threadRow = tid / (BN / TN);   // 0..15

    A += (size_t)cRow * BM * K;
    W += cCol * BN;
    C += (size_t)cRow * BM * N + cCol * BN;

    // A tile loader: BM x BK = 1024 floats, one float4 per thread
    const int innerRowA = tid / (BK / 4);    // 0..127
    const int innerColA = tid % (BK / 4);    // 0..1
    // B tile loader: BK x BN = 1024 floats, one float4 per thread
    const int innerRowB = tid / (BN / 4);    // 0..7
    const int innerColB = tid % (BN / 4);    // 0..31

    float acc[TM][TN];
#pragma unroll
    for (int i = 0; i < TM; i++)
#pragma unroll
        for (int j = 0; j < TN; j++) acc[i][j] = 0.0f;

    float regM[TM];
    float regN[TN];

    for (int bk = 0; bk < K; bk += BK) {
        // Load A tile (transpose into As)
        float4 ta = *reinterpret_cast<const float4*>(
            &A[(size_t)innerRowA * K + innerColA * 4]);
        As[(innerColA * 4 + 0) * BM + innerRowA] = ta.x;
        As[(innerColA * 4 + 1) * BM + innerRowA] = ta.y;
        As[(innerColA * 4 + 2) * BM + innerRowA] = ta.z;
        As[(innerColA * 4 + 3) * BM + innerRowA] = ta.w;
        // Load B tile
        *reinterpret_cast<float4*>(&Bs[innerRowB * BN + innerColB * 4]) =
            *reinterpret_cast<const float4*>(&W[(size_t)innerRowB * N + innerColB * 4]);
        __syncthreads();

        A += BK;
        W += (size_t)BK * N;

#pragma unroll
        for (int k = 0; k < BK; k++) {
            float4 m0 = *reinterpret_cast<const float4*>(&As[k * BM + threadRow * TM]);
            float4 m1 = *reinterpret_cast<const float4*>(&As[k * BM + threadRow * TM + 4]);
            float4 n0 = *reinterpret_cast<const float4*>(&Bs[k * BN + threadCol * TN]);
            float4 n1 = *reinterpret_cast<const float4*>(&Bs[k * BN + threadCol * TN + 4]);
            regM[0] = m0.x; regM[1] = m0.y; regM[2] = m0.z; regM[3] = m0.w;
            regM[4] = m1.x; regM[5] = m1.y; regM[6] = m1.z; regM[7] = m1.w;
            regN[0] = n0.x; regN[1] = n0.y; regN[2] = n0.z; regN[3] = n0.w;
            regN[4] = n1.x; regN[5] = n1.y; regN[6] = n1.z; regN[7] = n1.w;
#pragma unroll
            for (int i = 0; i < TM; i++)
#pragma unroll
                for (int j = 0; j < TN; j++)
                    acc[i][j] += regM[i] * regN[j];
        }
        __syncthreads();
    }

    // Epilogue: add bias, vectorized stores
    float4 bv0 = *reinterpret_cast<const float4*>(&bias[cCol * BN + threadCol * TN]);
    float4 bv1 = *reinterpret_cast<const float4*>(&bias[cCol * BN + threadCol * TN + 4]);
#pragma unroll
    for (int i = 0; i < TM; i++) {
        int row = threadRow * TM + i;
        float4 o0, o1;
        o0.x = acc[i][0] + bv0.x; o0.y = acc[i][1] + bv0.y;
        o0.z = acc[i][2] + bv0.z; o0.w = acc[i][3] + bv0.w;
        o1.x = acc[i][4] + bv1.x; o1.y = acc[i][5] + bv1.y;
        o1.z = acc[i][6] + bv1.z; o1.w = acc[i][7] + bv1.w;
        *reinterpret_cast<float4*>(&C[(size_t)row * N + threadCol * TN]) = o0;
        *reinterpret_cast<float4*>(&C[(size_t)row * N + threadCol * TN + 4]) = o1;
    }
}

// ---------------------------------------------------------------------------
// Anchor attention: one warp per (b, h, s). Reads g_qkv, writes g_att.
// ---------------------------------------------------------------------------
__global__ __launch_bounds__(256)
void anchor_attn_kernel(const float* __restrict__ gs) {
    const int gw = (blockIdx.x * blockDim.x + threadIdx.x) >> 5;  // global warp id
    const int lane = threadIdx.x & 31;
    // grid sized exactly: gw in [0, BB*NH*SS)

    const int s = gw % SS;
    const int h = (gw / SS) % NH;
    const int b = gw / (SS * NH);

    // group log-weights: log(softmax(group_scale))
    const float g0 = gs[0], g1 = gs[1], g2 = gs[2];
    const float mx = fmaxf(g0, fmaxf(g1, g2));
    const float lse = mx + logf(expf(g0 - mx) + expf(g1 - mx) + expf(g2 - mx));
    const float lw0 = g0 - lse, lw1 = g1 - lse, lw2 = g2 - lse;

    const float* base = g_qkv + (size_t)b * SS * N_QKV;
    const int hc = h * HD + lane * 4;

    const float4 q = *reinterpret_cast<const float4*>(
        base + (size_t)s * N_QKV + hc);

    int aidx[SIGMA];
    const int offs[10] = {-3, -2, -1, 1, 2, 3, -10, -5, 5, 10};
#pragma unroll
    for (int a = 0; a < 10; a++) {
        int j = s + offs[a];
        aidx[a] = j < 0 ? 0 : (j > SS - 1 ? SS - 1 : j);
    }
    aidx[10] = 0;
    aidx[11] = SS - 1;

    const float scale = 0.08838834764831845f;  // 128^-0.5
    float sc[SIGMA];
#pragma unroll
    for (int a = 0; a < SIGMA; a++) {
        const float4 kv = *reinterpret_cast<const float4*>(
            base + (size_t)aidx[a] * N_QKV + DIM + hc);
        float d = q.x * kv.x + q.y * kv.y + q.z * kv.z + q.w * kv.w;
#pragma unroll
        for (int o = 16; o > 0; o >>= 1)
            d += __shfl_xor_sync(0xffffffffu, d, o);
        const float lw = (a < 6) ? lw0 : ((a < 10) ? lw1 : lw2);
        sc[a] = d * scale + lw;
    }

    float m = sc[0];
#pragma unroll
    for (int a = 1; a < SIGMA; a++) m = fmaxf(m, sc[a]);
    float sum = 0.0f;
#pragma unroll
    for (int a = 0; a < SIGMA; a++) {
        sc[a] = __expf(sc[a] - m);
        sum += sc[a];
    }
    const float inv = 1.0f / sum;

    float4 acc = make_float4(0.f, 0.f, 0.f, 0.f);
#pragma unroll
    for (int a = 0; a < SIGMA; a++) {
        const float w = sc[a] * inv;
        const float4 vv = *reinterpret_cast<const float4*>(
            base + (size_t)aidx[a] * N_QKV + 2 * DIM + hc);
        acc.x += w * vv.x;
        acc.y += w * vv.y;
        acc.z += w * vv.z;
        acc.w += w * vv.w;
    }

    *reinterpret_cast<float4*>(
        g_att + (size_t)(b * SS + s) * DIM + hc) = acc;
}

// ---------------------------------------------------------------------------
extern "C" void kernel_launch(void* const* d_in, const int* in_sizes, int n_in,
                              void* d_out, int out_size) {
    const float* x    = (const float*)d_in[0];  // (B, S, DIM)
    const float* Wqkv = (const float*)d_in[1];  // (DIM, 3*DIM)
    const float* bqkv = (const float*)d_in[2];  // (3*DIM,)
    const float* Wout = (const float*)d_in[3];  // (DIM, DIM)
    const float* bout = (const float*)d_in[4];  // (DIM,)
    const float* gsc  = (const float*)d_in[5];  // (3,)
    float* out = (float*)d_out;                 // (B, S, DIM)

    float* qkv_ptr = nullptr;
    float* att_ptr = nullptr;
    cudaGetSymbolAddress((void**)&qkv_ptr, g_qkv);
    cudaGetSymbolAddress((void**)&att_ptr, g_att);

    constexpr int BM = 128, BN = 128, BK = 8, TM = 8, TN = 8;
    constexpr int THREADS = (BM / TM) * (BN / TN);  // 256

    // 1) QKV projection: (4096 x 1536) @ (1536 x 4608) + bqkv
    {
        dim3 grid(N_QKV / BN, M_TOT / BM);
        sgemm_bias<BM, BN, BK, TM, TN><<<grid, THREADS>>>(
            M_TOT, N_QKV, DIM, x, Wqkv, bqkv, qkv_ptr);
    }

    // 2) Anchor attention: one warp per (b, h, s)
    {
        const int total_warps = BB * NH * SS;          // 49152
        const int threads = 256;
        const int blocks = total_warps * 32 / threads; // 6144
        anchor_attn_kernel<<<blocks, threads>>>(gsc);
    }

    // 3) Output projection: (4096 x 1536) @ (1536 x 1536) + bout
    {
        dim3 grid(DIM / BN, M_TOT / BM);
        sgemm_bias<BM, BN, BK, TM, TN><<<grid, THREADS>>>(
            M_TOT, DIM, DIM, att_ptr, Wout, bout, out);
    }
}

// round 3
// speedup vs baseline: 3.9129x; 3.9129x over previous
#include <cuda_runtime.h>
#include <cstdint>
#include <math.h>

#define BB 2
#define SS 2048
#define DIM 1536
#define NH 12
#define HD 128
#define SIGMA 12
#define M_TOT (BB * SS)      // 4096
#define N_QKV (3 * DIM)      // 4608

// ---------------- scratch (__device__ globals; allocation-free rule) -------
__device__ float g_x[(size_t)M_TOT * DIM];        // tf32-rounded x
__device__ float g_wqkvT[(size_t)N_QKV * DIM];    // Wqkv^T, tf32-rounded
__device__ float g_woutT[(size_t)DIM * DIM];      // Wout^T, tf32-rounded
__device__ float g_qkv[(size_t)M_TOT * N_QKV];    // QKV proj output (fp32)
__device__ float g_att[(size_t)M_TOT * DIM];      // attention out (tf32-rounded)

// ---------------- helpers ---------------------------------------------------
__device__ __forceinline__ uint32_t smem_u32(const void* p) {
    uint32_t a;
    asm("{ .reg .u64 t; cvta.to.shared.u64 t, %1; cvt.u32.u64 %0, t; }"
        : "=r"(a) : "l"(p));
    return a;
}
__device__ __forceinline__ float rna_tf32(float x) {
    uint32_t r;
    asm("cvt.rna.tf32.f32 %0, %1;" : "=r"(r) : "f"(x));
    return __uint_as_float(r);
}
__device__ __forceinline__ void cp16(uint32_t dst, const void* src) {
    asm volatile("cp.async.cg.shared.global [%0], [%1], 16;"
                 :: "r"(dst), "l"(src) : "memory");
}
__device__ __forceinline__ void cp_commit() {
    asm volatile("cp.async.commit_group;" ::: "memory");
}
template <int N>
__device__ __forceinline__ void cp_wait() {
    asm volatile("cp.async.wait_group %0;" :: "n"(N) : "memory");
}
__device__ __forceinline__ void mma_tf32(float* c, const uint32_t* a, const uint32_t* b) {
    asm volatile(
        "mma.sync.aligned.m16n8k8.row.col.f32.tf32.tf32.f32 "
        "{%0,%1,%2,%3}, {%4,%5,%6,%7}, {%8,%9}, {%0,%1,%2,%3};"
        : "+f"(c[0]), "+f"(c[1]), "+f"(c[2]), "+f"(c[3])
        : "r"(a[0]), "r"(a[1]), "r"(a[2]), "r"(a[3]), "r"(b[0]), "r"(b[1]));
}

// ---------------- tf32 mma.sync GEMM ----------------------------------------
// C[M,N] = A[M,K] @ BT^T + bias, A:[M,K] row-major, BT:[N,K] row-major.
// CTA tile 128x128, BK=32 floats (128B rows, SW128 swizzle), 8 warps (2m x 4n),
// warp tile 64x32, fragments m16n8k8. 3-stage cp.async pipeline.
#define BM 128
#define BN 128
#define BKF 32
#define STAGES 3
#define A_ST 16384            // BM * 128B
#define B_ST 16384            // BN * 128B
#define STAGE_BYTES (A_ST + B_ST)
#define GSMEM (STAGES * STAGE_BYTES)   // 98304

__global__ __launch_bounds__(256, 2)
void gemm_tf32_mma(const float* __restrict__ A, const float* __restrict__ BT,
                   const float* __restrict__ bias, float* __restrict__ C,
                   int Ndim, int K) {
    extern __shared__ char smem[];
    const int tid = threadIdx.x;
    const int wid = tid >> 5;
    const int lane = tid & 31;
    const int g = lane >> 2;        // 0..7
    const int t = lane & 3;         // 0..3
    const int warp_m = wid >> 2;    // 0..1
    const int warp_n = wid & 3;     // 0..3
    const int m0 = blockIdx.y * BM;
    const int n0 = blockIdx.x * BN;
    const int KT = K / BKF;

    const int ld_row = tid >> 3;          // 0..31 within each i-block
    const int ld_seg = tid & 7;           // 16B chunk within 128B row

    // stage loader: A rows 0..127, B rows 0..127; 4 chunks each per thread
    auto load_stage = [&](int stage, int kt) {
        const float* Ak = A + (size_t)m0 * K + kt * BKF;
        const float* Bk = BT + (size_t)n0 * K + kt * BKF;
        char* sA = smem + stage * STAGE_BYTES;
        char* sB = sA + A_ST;
#pragma unroll
        for (int i = 0; i < 4; i++) {
            int row = i * 32 + ld_row;
            uint32_t dst = smem_u32(sA) + row * 128 + ((ld_seg ^ (row & 7)) * 16);
            cp16(dst, Ak + (size_t)row * K + ld_seg * 4);
        }
#pragma unroll
        for (int i = 0; i < 4; i++) {
            int row = i * 32 + ld_row;
            uint32_t dst = smem_u32(sB) + row * 128 + ((ld_seg ^ (row & 7)) * 16);
            cp16(dst, Bk + (size_t)row * K + ld_seg * 4);
        }
        cp_commit();
    };

    float acc[4][4][4];
#pragma unroll
    for (int i = 0; i < 4; i++)
#pragma unroll
        for (int j = 0; j < 4; j++)
#pragma unroll
            for (int r = 0; r < 4; r++) acc[i][j][r] = 0.0f;

    // prefetch
    for (int s = 0; s < STAGES - 1; s++) load_stage(s, s);

    for (int kt = 0; kt < KT; ++kt) {
        cp_wait<STAGES - 2>();
        __syncthreads();

        if (kt + STAGES - 1 < KT)
            load_stage((kt + STAGES - 1) % STAGES, kt + STAGES - 1);

        const char* sA = smem + (kt % STAGES) * STAGE_BYTES;
        const char* sB = sA + A_ST;
        // per-thread base offsets (bytes) into the swizzled tiles
        const uint32_t a_base = (warp_m * 64 + g) * 128 + t * 4;
        const uint32_t b_base = (warp_n * 32 + g) * 128 + t * 4;

#pragma unroll
        for (int ks = 0; ks < 4; ks++) {
            const uint32_t so = ((2 * ks) ^ g) * 16;
            uint32_t afr[4][4];
#pragma unroll
            for (int mt = 0; mt < 4; mt++) {
                uint32_t o = a_base + mt * 2048 + so;
                afr[mt][0] = __float_as_uint(*(const float*)(sA + o));
                afr[mt][1] = __float_as_uint(*(const float*)(sA + o + 1024));
                afr[mt][2] = __float_as_uint(*(const float*)(sA + (o ^ 16)));
                afr[mt][3] = __float_as_uint(*(const float*)(sA + (o ^ 16) + 1024));
            }
            uint32_t bfr[4][2];
#pragma unroll
            for (int nt = 0; nt < 4; nt++) {
                uint32_t o = b_base + nt * 1024 + so;
                bfr[nt][0] = __float_as_uint(*(const float*)(sB + o));
                bfr[nt][1] = __float_as_uint(*(const float*)(sB + (o ^ 16)));
            }
#pragma unroll
            for (int mt = 0; mt < 4; mt++)
#pragma unroll
                for (int nt = 0; nt < 4; nt++)
                    mma_tf32(acc[mt][nt], afr[mt], bfr[nt]);
        }
        __syncthreads();
    }

    // epilogue
#pragma unroll
    for (int mt = 0; mt < 4; mt++) {
        const int r0 = m0 + warp_m * 64 + mt * 16 + g;
#pragma unroll
        for (int nt = 0; nt < 4; nt++) {
            const int col = n0 + warp_n * 32 + nt * 8 + 2 * t;
            const float2 bv = *reinterpret_cast<const float2*>(bias + col);
            float2 o0, o1;
            o0.x = acc[mt][nt][0] + bv.x;
            o0.y = acc[mt][nt][1] + bv.y;
            o1.x = acc[mt][nt][2] + bv.x;
            o1.y = acc[mt][nt][3] + bv.y;
            *reinterpret_cast<float2*>(C + (size_t)r0 * Ndim + col) = o0;
            *reinterpret_cast<float2*>(C + (size_t)(r0 + 8) * Ndim + col) = o1;
        }
    }
}

// ---------------- pre-pass kernels -----------------------------------------
__global__ __launch_bounds__(256)
void round_x_kernel(const float* __restrict__ in, float* __restrict__ out, int n4) {
    int i = blockIdx.x * blockDim.x + threadIdx.x;
    if (i < n4) {
        float4 v = reinterpret_cast<const float4*>(in)[i];
        v.x = rna_tf32(v.x); v.y = rna_tf32(v.y);
        v.z = rna_tf32(v.z); v.w = rna_tf32(v.w);
        reinterpret_cast<float4*>(out)[i] = v;
    }
}

// in: R x C row-major; out: C x R row-major, tf32-rounded
__global__ __launch_bounds__(1024)
void transpose_rna_kernel(const float* __restrict__ in, float* __restrict__ out,
                          int R, int C) {
    __shared__ float tbuf[32][33];
    int c = blockIdx.x * 32 + threadIdx.x;
    int r = blockIdx.y * 32 + threadIdx.y;
    tbuf[threadIdx.y][threadIdx.x] = in[(size_t)r * C + c];
    __syncthreads();
    int oc = blockIdx.y * 32 + threadIdx.x;
    int orow = blockIdx.x * 32 + threadIdx.y;
    out[(size_t)orow * R + oc] = rna_tf32(tbuf[threadIdx.x][threadIdx.y]);
}

// ---------------- anchor attention (one warp per (b,h,s)) -------------------
__global__ __launch_bounds__(256)
void anchor_attn_kernel(const float* __restrict__ gs) {
    const int gw = (blockIdx.x * blockDim.x + threadIdx.x) >> 5;
    const int lane = threadIdx.x & 31;

    const int s = gw % SS;
    const int h = (gw / SS) % NH;
    const int b = gw / (SS * NH);

    const float g0 = gs[0], g1 = gs[1], g2 = gs[2];
    const float mx = fmaxf(g0, fmaxf(g1, g2));
    const float lse = mx + logf(expf(g0 - mx) + expf(g1 - mx) + expf(g2 - mx));
    const float lw0 = g0 - lse, lw1 = g1 - lse, lw2 = g2 - lse;

    const float* base = g_qkv + (size_t)b * SS * N_QKV;
    const int hc = h * HD + lane * 4;

    const float4 q = *reinterpret_cast<const float4*>(base + (size_t)s * N_QKV + hc);

    int aidx[SIGMA];
    const int offs[10] = {-3, -2, -1, 1, 2, 3, -10, -5, 5, 10};
#pragma unroll
    for (int a = 0; a < 10; a++) {
        int j = s + offs[a];
        aidx[a] = j < 0 ? 0 : (j > SS - 1 ? SS - 1 : j);
    }
    aidx[10] = 0;
    aidx[11] = SS - 1;

    const float scale = 0.08838834764831845f;
    float sc[SIGMA];
#pragma unroll
    for (int a = 0; a < SIGMA; a++) {
        const float4 kv = *reinterpret_cast<const float4*>(
            base + (size_t)aidx[a] * N_QKV + DIM + hc);
        float d = q.x * kv.x + q.y * kv.y + q.z * kv.z + q.w * kv.w;
#pragma unroll
        for (int o = 16; o > 0; o >>= 1)
            d += __shfl_xor_sync(0xffffffffu, d, o);
        const float lw = (a < 6) ? lw0 : ((a < 10) ? lw1 : lw2);
        sc[a] = d * scale + lw;
    }

    float m = sc[0];
#pragma unroll
    for (int a = 1; a < SIGMA; a++) m = fmaxf(m, sc[a]);
    float sum = 0.0f;
#pragma unroll
    for (int a = 0; a < SIGMA; a++) { sc[a] = __expf(sc[a] - m); sum += sc[a]; }
    const float inv = 1.0f / sum;

    float4 acc = make_float4(0.f, 0.f, 0.f, 0.f);
#pragma unroll
    for (int a = 0; a < SIGMA; a++) {
        const float w = sc[a] * inv;
        const float4 vv = *reinterpret_cast<const float4*>(
            base + (size_t)aidx[a] * N_QKV + 2 * DIM + hc);
        acc.x += w * vv.x; acc.y += w * vv.y;
        acc.z += w * vv.z; acc.w += w * vv.w;
    }
    acc.x = rna_tf32(acc.x); acc.y = rna_tf32(acc.y);
    acc.z = rna_tf32(acc.z); acc.w = rna_tf32(acc.w);

    *reinterpret_cast<float4*>(g_att + (size_t)(b * SS + s) * DIM + hc) = acc;
}

// ---------------------------------------------------------------------------
extern "C" void kernel_launch(void* const* d_in, const int* in_sizes, int n_in,
                              void* d_out, int out_size) {
    const float* x    = (const float*)d_in[0];
    const float* Wqkv = (const float*)d_in[1];
    const float* bqkv = (const float*)d_in[2];
    const float* Wout = (const float*)d_in[3];
    const float* bout = (const float*)d_in[4];
    const float* gsc  = (const float*)d_in[5];
    float* out = (float*)d_out;

    float *px, *pwqkvT, *pwoutT, *pqkv, *patt;
    cudaGetSymbolAddress((void**)&px, g_x);
    cudaGetSymbolAddress((void**)&pwqkvT, g_wqkvT);
    cudaGetSymbolAddress((void**)&pwoutT, g_woutT);
    cudaGetSymbolAddress((void**)&pqkv, g_qkv);
    cudaGetSymbolAddress((void**)&patt, g_att);

    static bool attr_set = false;
    if (!attr_set) {
        cudaFuncSetAttribute(gemm_tf32_mma,
                             cudaFuncAttributeMaxDynamicSharedMemorySize, GSMEM);
        attr_set = true;
    }

    // 1) tf32-round x
    {
        int n4 = M_TOT * DIM / 4;
        round_x_kernel<<<(n4 + 255) / 256, 256>>>(x, px, n4);
    }
    // 2) transpose + round weights
    transpose_rna_kernel<<<dim3(N_QKV / 32, DIM / 32), dim3(32, 32)>>>(Wqkv, pwqkvT, DIM, N_QKV);
    transpose_rna_kernel<<<dim3(DIM / 32, DIM / 32), dim3(32, 32)>>>(Wout, pwoutT, DIM, DIM);

    // 3) QKV projection: (4096x1536) @ (1536x4608)
    gemm_tf32_mma<<<dim3(N_QKV / BN, M_TOT / BM), 256, GSMEM>>>(
        px, pwqkvT, bqkv, pqkv, N_QKV, DIM);

    // 4) anchor attention
    {
        const int total_warps = BB * NH * SS;
        anchor_attn_kernel<<<total_warps * 32 / 256, 256>>>(gsc);
    }

    // 5) output projection: (4096x1536) @ (1536x1536)
    gemm_tf32_mma<<<dim3(DIM / BN, M_TOT / BM), 256, GSMEM>>>(
        patt, pwoutT, bout, out, DIM, DIM);
}